// round 7
// baseline (speedup 1.0000x reference)
#include <cuda_runtime.h>
#include <cstdint>

typedef unsigned long long ull;
#define FULL 0xFFFFFFFFu

constexpr int NUM_GROUP  = 512;
constexpr int GROUP_SIZE = 32;
constexpr int TPB        = 512;
constexpr int MAXB       = 64;

__device__ int g_prog[MAXB];

__global__ void init_prog() {
    if (threadIdx.x < MAXB) g_prog[threadIdx.x] = 0;
}

// ---- packed f32x2 helpers (sm_100+) ----
__device__ __forceinline__ ull pack2(float a, float b) {
    ull r; asm("mov.b64 %0,{%1,%2};" : "=l"(r) : "f"(a), "f"(b)); return r;
}
__device__ __forceinline__ void unpack2(ull v, float& a, float& b) {
    asm("mov.b64 {%0,%1},%2;" : "=f"(a), "=f"(b) : "l"(v));
}
__device__ __forceinline__ ull addx2(ull a, ull b) {
    ull r; asm("add.rn.f32x2 %0,%1,%2;" : "=l"(r) : "l"(a), "l"(b)); return r;
}
__device__ __forceinline__ ull mulx2(ull a, ull b) {
    ull r; asm("mul.rn.f32x2 %0,%1,%2;" : "=l"(r) : "l"(a), "l"(b)); return r;
}
__device__ __forceinline__ ull fma2_(ull a, ull b, ull c) {
    ull r; asm("fma.rn.f32x2 %0,%1,%2,%3;" : "=l"(r) : "l"(a), "l"(b), "l"(c)); return r;
}
__device__ __forceinline__ uint32_t redux_max_u32(uint32_t v) {
    uint32_t r; asm("redux.sync.max.u32 %0, %1, 0xffffffff;" : "=r"(r) : "r"(v)); return r;
}
__device__ __forceinline__ uint32_t redux_min_u32(uint32_t v) {
    uint32_t r; asm("redux.sync.min.u32 %0, %1, 0xffffffff;" : "=r"(r) : "r"(v)); return r;
}
__device__ __forceinline__ void st_release_gpu(int* p, int v) {
    asm volatile("st.release.gpu.global.s32 [%0], %1;" :: "l"(p), "r"(v) : "memory");
}
__device__ __forceinline__ int ld_acquire_gpu(const int* p) {
    int v; asm volatile("ld.acquire.gpu.global.s32 %0, [%1];" : "=r"(v) : "l"(p) : "memory");
    return v;
}

// ---- cluster / DSMEM helpers ----
__device__ __forceinline__ uint32_t smem_u32(const void* p) {
    uint32_t a;
    asm("{ .reg .u64 t; cvta.to.shared.u64 t, %1; cvt.u32.u64 %0, t; }"
        : "=r"(a) : "l"(p));
    return a;
}
__device__ __forceinline__ uint32_t cluster_rank() {
    uint32_t r; asm("mov.u32 %0, %%cluster_ctarank;" : "=r"(r)); return r;
}
__device__ __forceinline__ uint32_t mapa_u32(uint32_t addr, uint32_t rank) {
    uint32_t r; asm("mapa.shared::cluster.u32 %0, %1, %2;" : "=r"(r) : "r"(addr), "r"(rank));
    return r;
}
__device__ __forceinline__ void st_cluster_u32(uint32_t addr, uint32_t v) {
    asm volatile("st.shared::cluster.u32 [%0], %1;" :: "r"(addr), "r"(v) : "memory");
}
__device__ __forceinline__ void st_release_cluster_remote(uint32_t addr, uint32_t v) {
    asm volatile("st.release.cluster.shared::cluster.u32 [%0], %1;" :: "r"(addr), "r"(v) : "memory");
}
__device__ __forceinline__ void st_release_cta_local(uint32_t addr, uint32_t v) {
    asm volatile("st.release.cluster.shared::cta.u32 [%0], %1;" :: "r"(addr), "r"(v) : "memory");
}
__device__ __forceinline__ uint32_t ld_acquire_shared(uint32_t addr) {
    uint32_t v;
    asm volatile("ld.acquire.cluster.shared::cta.u32 %0, [%1];" : "=r"(v) : "r"(addr) : "memory");
    return v;
}

// ============================================================
// Fused kernel, TPB=512, cluster(2,1,1):
//   blocks [0, 2B)        : FPS, 2 CTAs (one cluster) per batch, half points each
//   blocks [2B, 2B + 32B) : kNN, 16 groups per block, batch-major order
// ============================================================
__global__ __launch_bounds__(TPB) __cluster_dims__(2, 1, 1)
void fused_kernel(const float* __restrict__ xyz,
                  float* __restrict__ nb,
                  float* __restrict__ centers,
                  int N, int B) {
    extern __shared__ float s[];
    const int tid  = threadIdx.x;
    const int lane = tid & 31;
    const int warp = tid >> 5;

    if (blockIdx.x < (unsigned)(2 * B)) {
        // ==================== FPS: cluster of 2, half the points each ====================
        const int b    = blockIdx.x >> 1;
        const uint32_t rank = cluster_rank();     // == blockIdx.x & 1
        const int half = N >> 1;

        const float* X = xyz + (size_t)b * 3 * N;
        const float* Y = X + N;
        const float* Z = Y + N;
        const float* Xh = X + rank * half;
        const float* Yh = Y + rank * half;
        const float* Zh = Z + rank * half;

        __shared__ uint32_t vbuf[2][32];        // per-warp value table (lanes 16..31 stay 0)
        __shared__ uint32_t idslot[2];          // rare multi-warp-tie resolution
        __shared__ uint32_t pkt[2][2][8];       // [side: 0=mine,1=theirs][parity][cx,cy,cz,val,seq,...]
        if (tid < 64) vbuf[tid >> 5][tid & 31] = 0u;
        if (tid < 2)  idslot[tid] = 0xFFFFFFFFu;
        if (tid < 4)  pkt[tid >> 1][tid & 1][4] = 0u;   // seq = 0
        __syncthreads();

        // cluster barrier: peer must not write my pkt before init completes
        asm volatile("barrier.cluster.arrive.aligned;" ::: "memory");
        asm volatile("barrier.cluster.wait.aligned;" ::: "memory");

        const uint32_t my_pkt0[2]  = { smem_u32(&pkt[0][0][0]), smem_u32(&pkt[0][1][0]) };
        const uint32_t th_pkt[2]   = { smem_u32(&pkt[1][0][0]), smem_u32(&pkt[1][1][0]) };
        const uint32_t peer_th[2]  = { mapa_u32(th_pkt[0], rank ^ 1), mapa_u32(th_pkt[1], rank ^ 1) };

        // 4 packed pairs per thread (half = 4096 at N=8192)
        ull  pxp[4], pyp[4], pzp[4];
        float md[8];
        const int NP = (half + 2 * TPB - 1) / (2 * TPB);
        #pragma unroll
        for (int i = 0; i < 4; i++) {
            if (i < NP) {
                int n0 = 2 * (tid + i * TPB);
                bool v = (n0 + 1 < half);
                float x0 = v ? Xh[n0] : 0.f, x1 = v ? Xh[n0 + 1] : 0.f;
                float y0 = v ? Yh[n0] : 0.f, y1 = v ? Yh[n0 + 1] : 0.f;
                float z0 = v ? Zh[n0] : 0.f, z1 = v ? Zh[n0 + 1] : 0.f;
                pxp[i] = pack2(x0, x1);
                pyp[i] = pack2(y0, y1);
                pzp[i] = pack2(z0, z1);
                md[2 * i]     = v ? 1e10f : -1.0f;
                md[2 * i + 1] = v ? 1e10f : -1.0f;
            }
        }

        float cx = X[0], cy = Y[0], cz = Z[0];
        float* cout = centers + (size_t)b * NUM_GROUP * 3;

        for (int it = 0; it < NUM_GROUP; it++) {
            const int p = it & 1;
            if (rank == 0 && tid == 0) {
                cout[it * 3 + 0] = cx;
                cout[it * 3 + 1] = cy;
                cout[it * 3 + 2] = cz;
                if ((it & 7) == 7) st_release_gpu(&g_prog[b], it - 7);   // lagged publish
            }
            if (it == NUM_GROUP - 1) break;    // last center stored; no more selection needed

            const ull ncx = pack2(-cx, -cx), ncy = pack2(-cy, -cy), ncz = pack2(-cz, -cz);

            // lean hot loop over my half
            float bm0 = -2.0f, bm1 = -2.0f;
            #pragma unroll
            for (int i = 0; i < 4; i++) {
                if (i < NP) {
                    ull dx = addx2(pxp[i], ncx);
                    ull dy = addx2(pyp[i], ncy);
                    ull dz = addx2(pzp[i], ncz);
                    ull m  = mulx2(dx, dx);
                    m = fma2_(dy, dy, m);
                    m = fma2_(dz, dz, m);      // == fmaf(dz,dz,fmaf(dy,dy,dx*dx)) per lane
                    float d0, d1; unpack2(m, d0, d1);
                    float m0 = fminf(md[2 * i],     d0);
                    float m1 = fminf(md[2 * i + 1], d1);
                    md[2 * i]     = m0;
                    md[2 * i + 1] = m1;
                    bm0 = fmaxf(bm0, m0);
                    bm1 = fmaxf(bm1, m1);
                }
            }
            float bv = fmaxf(bm0, bm1);

            uint32_t fb   = (bv >= 0.0f) ? __float_as_uint(bv) : 0u;
            uint32_t wmax = redux_max_u32(fb);
            if (lane == 0) vbuf[p][warp] = wmax;
            __syncthreads();                              // the one barrier

            if (tid == TPB - 1) idslot[p ^ 1] = 0xFFFFFFFFu;   // reset for next iteration

            uint32_t v2 = vbuf[p][lane];
            uint32_t m2 = redux_max_u32(v2);              // local block max
            unsigned tiemask = __ballot_sync(FULL, v2 == m2) & 0xFFFFu;
            const uint32_t seq = (uint32_t)(it + 1);

            if (__popc(tiemask) == 1) {
                // fast path: single winner warp resolves index + centroid from registers
                if (warp == (__ffs(tiemask) - 1)) {
                    int jb = -1;
                    #pragma unroll
                    for (int j = 7; j >= 0; j--)
                        if ((j >> 1) < NP && md[j] == bv) jb = j;   // smallest j = smallest id
                    uint32_t q = (fb == m2) ? (uint32_t)(2 * (tid + (jb >> 1) * TPB) + (jb & 1))
                                            : 0xFFFFFFFFu;
                    uint32_t idmin = redux_min_u32(q);
                    if (q == idmin) {
                        float a0, a1, b0, b1, c0, c1;
                        unpack2(pxp[jb >> 1], a0, a1);
                        unpack2(pyp[jb >> 1], b0, b1);
                        unpack2(pzp[jb >> 1], c0, c1);
                        float wx = (jb & 1) ? a1 : a0;
                        float wy = (jb & 1) ? b1 : b0;
                        float wz = (jb & 1) ? c1 : c0;
                        // own packet
                        pkt[0][p][0] = __float_as_uint(wx);
                        pkt[0][p][1] = __float_as_uint(wy);
                        pkt[0][p][2] = __float_as_uint(wz);
                        pkt[0][p][3] = m2;
                        st_release_cta_local(my_pkt0[p] + 16, seq);
                        // peer's "theirs" packet
                        uint32_t ra = peer_th[p];
                        st_cluster_u32(ra + 0,  __float_as_uint(wx));
                        st_cluster_u32(ra + 4,  __float_as_uint(wy));
                        st_cluster_u32(ra + 8,  __float_as_uint(wz));
                        st_cluster_u32(ra + 12, m2);
                        st_release_cluster_remote(ra + 16, seq);
                    }
                }
            } else {
                // rare exact-tie path across warps (block-uniform branch)
                uint32_t q = 0xFFFFFFFFu;
                if (wmax == m2) {
                    int jb = -1;
                    #pragma unroll
                    for (int j = 7; j >= 0; j--)
                        if ((j >> 1) < NP && md[j] == bv) jb = j;
                    q = (fb == m2) ? (uint32_t)(2 * (tid + (jb >> 1) * TPB) + (jb & 1))
                                   : 0xFFFFFFFFu;
                    uint32_t idw = redux_min_u32(q);
                    if (lane == 0) atomicMin(&idslot[p], idw);
                }
                __syncthreads();
                if (wmax == m2 && q == idslot[p]) {
                    int jb = -1;
                    #pragma unroll
                    for (int j = 7; j >= 0; j--)
                        if ((j >> 1) < NP && md[j] == bv) jb = j;
                    float a0, a1, b0, b1, c0, c1;
                    unpack2(pxp[jb >> 1], a0, a1);
                    unpack2(pyp[jb >> 1], b0, b1);
                    unpack2(pzp[jb >> 1], c0, c1);
                    float wx = (jb & 1) ? a1 : a0;
                    float wy = (jb & 1) ? b1 : b0;
                    float wz = (jb & 1) ? c1 : c0;
                    pkt[0][p][0] = __float_as_uint(wx);
                    pkt[0][p][1] = __float_as_uint(wy);
                    pkt[0][p][2] = __float_as_uint(wz);
                    pkt[0][p][3] = m2;
                    st_release_cta_local(my_pkt0[p] + 16, seq);
                    uint32_t ra = peer_th[p];
                    st_cluster_u32(ra + 0,  __float_as_uint(wx));
                    st_cluster_u32(ra + 4,  __float_as_uint(wy));
                    st_cluster_u32(ra + 8,  __float_as_uint(wz));
                    st_cluster_u32(ra + 12, m2);
                    st_release_cluster_remote(ra + 16, seq);
                }
            }

            // all threads: wait for both packets, pick global winner
            while (ld_acquire_shared(my_pkt0[p] + 16) < seq) { }
            while (ld_acquire_shared(th_pkt[p] + 16)  < seq) { }
            uint32_t mv = pkt[0][p][3];
            uint32_t tv = pkt[1][p][3];
            bool use_mine = (mv > tv) || (mv == tv && rank == 0);  // ties -> block 0 (smaller ids)
            const uint32_t* src = use_mine ? &pkt[0][p][0] : &pkt[1][p][0];
            cx = __uint_as_float(src[0]);
            cy = __uint_as_float(src[1]);
            cz = __uint_as_float(src[2]);
        }
        if (rank == 0 && tid == 0) st_release_gpu(&g_prog[b], NUM_GROUP);
    } else {
        // ==================== kNN top-32 (batch-major block order) ====================
        float* sx = s;
        float* sy = s + N;
        float* sz = s + 2 * N;

        const int kb    = blockIdx.x - 2 * B;
        const int b     = kb % B;
        const int chunk = kb / B;
        const int g     = chunk * 16 + warp;

        const float* X = xyz + (size_t)b * 3 * N;
        const float4* X4 = (const float4*)X;
        float4* sx4 = (float4*)sx;
        float4* sy4 = (float4*)sy;
        float4* sz4 = (float4*)sz;
        const int N4 = N >> 2;
        for (int n = tid; n < N4; n += TPB) {
            sx4[n] = X4[n];
            sy4[n] = X4[N4 + n];
            sz4[n] = X4[2 * N4 + n];
        }
        __syncthreads();

        while (ld_acquire_gpu(&g_prog[b]) < g + 1) __nanosleep(128);

        const float* c = centers + ((size_t)b * NUM_GROUP + g) * 3;
        const float cx = __ldcg(&c[0]), cy = __ldcg(&c[1]), cz = __ldcg(&c[2]);

        // init with first 32 points, bitonic sort ascending u64 keys
        ull key;
        {
            float dx = sx[lane] - cx, dy = sy[lane] - cy, dz = sz[lane] - cz;
            float d2 = fmaf(dz, dz, fmaf(dy, dy, dx * dx));
            key = ((ull)__float_as_uint(d2) << 32) | (uint32_t)lane;
        }
        #pragma unroll
        for (int k2 = 2; k2 <= 32; k2 <<= 1) {
            #pragma unroll
            for (int j = k2 >> 1; j > 0; j >>= 1) {
                ull partner = __shfl_xor_sync(FULL, key, j);
                bool lower  = (lane & j) == 0;
                bool asc    = (lane & k2) == 0;
                ull mn = (key < partner) ? key : partner;
                ull mx = (key < partner) ? partner : key;
                key = (lower == asc) ? mn : mx;
            }
        }
        ull kmax = __shfl_sync(FULL, key, 31);

        // scalar step for points [32, 64)
        {
            int idx = 32 + lane;
            float dx = sx[idx] - cx, dy = sy[idx] - cy, dz = sz[idx] - cz;
            float d2 = fmaf(dz, dz, fmaf(dy, dy, dx * dx));
            ull nk = ((ull)__float_as_uint(d2) << 32) | (uint32_t)idx;
            unsigned mask = __ballot_sync(FULL, nk < kmax);
            while (mask) {
                int src = __ffs(mask) - 1;
                mask &= mask - 1;
                ull cand = __shfl_sync(FULL, nk, src);
                if (cand >= kmax) continue;
                int pos = __popc(__ballot_sync(FULL, key < cand));
                ull up  = __shfl_up_sync(FULL, key, 1);
                if (lane == pos)      key = cand;
                else if (lane > pos)  key = up;
                kmax = __shfl_sync(FULL, key, 31);
            }
        }

        // packed stream: 64 candidates per step
        const float2* sx2 = (const float2*)sx;
        const float2* sy2 = (const float2*)sy;
        const float2* sz2 = (const float2*)sz;
        const ull ncx = pack2(-cx, -cx), ncy = pack2(-cy, -cy), ncz = pack2(-cz, -cz);

        for (int base = 64; base < N; base += 64) {
            int h = (base >> 1) + lane;
            float2 xx = sx2[h], yy = sy2[h], zz = sz2[h];
            ull dx = addx2(pack2(xx.x, xx.y), ncx);
            ull dy = addx2(pack2(yy.x, yy.y), ncy);
            ull dz = addx2(pack2(zz.x, zz.y), ncz);
            ull m  = mulx2(dx, dx);
            m = fma2_(dy, dy, m);
            m = fma2_(dz, dz, m);
            float d0, d1; unpack2(m, d0, d1);
            int i0 = base + 2 * lane;
            ull k0 = ((ull)__float_as_uint(d0) << 32) | (uint32_t)i0;
            ull k1 = ((ull)__float_as_uint(d1) << 32) | (uint32_t)(i0 + 1);

            unsigned m0 = __ballot_sync(FULL, k0 < kmax);
            unsigned m1 = __ballot_sync(FULL, k1 < kmax);
            while (m0) {
                int src = __ffs(m0) - 1;
                m0 &= m0 - 1;
                ull cand = __shfl_sync(FULL, k0, src);
                if (cand >= kmax) continue;
                int pos = __popc(__ballot_sync(FULL, key < cand));
                ull up  = __shfl_up_sync(FULL, key, 1);
                if (lane == pos)      key = cand;
                else if (lane > pos)  key = up;
                kmax = __shfl_sync(FULL, key, 31);
            }
            while (m1) {
                int src = __ffs(m1) - 1;
                m1 &= m1 - 1;
                ull cand = __shfl_sync(FULL, k1, src);
                if (cand >= kmax) continue;
                int pos = __popc(__ballot_sync(FULL, key < cand));
                ull up  = __shfl_up_sync(FULL, key, 1);
                if (lane == pos)      key = cand;
                else if (lane > pos)  key = up;
                kmax = __shfl_sync(FULL, key, 31);
            }
        }

        // emit: neighborhood = point - center (lane-sorted ascending = top_k order)
        int idx = (int)(uint32_t)key;
        float ox = sx[idx] - cx, oy = sy[idx] - cy, oz = sz[idx] - cz;
        size_t o = (((size_t)b * NUM_GROUP + g) * GROUP_SIZE + lane) * 3;
        nb[o + 0] = ox;
        nb[o + 1] = oy;
        nb[o + 2] = oz;
    }
}

// ============================================================
extern "C" void kernel_launch(void* const* d_in, const int* in_sizes, int n_in,
                              void* d_out, int out_size) {
    const float* xyz = (const float*)d_in[0];
    float* out = (float*)d_out;

    const int B = out_size / (NUM_GROUP * (GROUP_SIZE + 1) * 3);
    const int N = in_sizes[0] / (3 * B);

    float* nb      = out;
    float* centers = out + (size_t)B * NUM_GROUP * GROUP_SIZE * 3;

    const int fpsBlocks = 2 * B;
    const int knnBlocks = B * (NUM_GROUP / 16);
    size_t smem = (size_t)3 * N * sizeof(float);
    if (smem < 120 * 1024) smem = 120 * 1024;   // force 1 block/SM

    init_prog<<<1, MAXB>>>();

    cudaFuncSetAttribute(fused_kernel, cudaFuncAttributeMaxDynamicSharedMemorySize, (int)smem);
    fused_kernel<<<fpsBlocks + knnBlocks, TPB, smem>>>(xyz, nb, centers, N, B);
}

// round 8
// speedup vs baseline: 1.4299x; 1.4299x over previous
#include <cuda_runtime.h>
#include <cstdint>

typedef unsigned long long ull;
#define FULL 0xFFFFFFFFu

constexpr int NUM_GROUP  = 512;
constexpr int GROUP_SIZE = 32;
constexpr int TPB        = 512;
constexpr int MAXB       = 64;

__device__ int g_prog[MAXB];

__global__ void init_prog() {
    if (threadIdx.x < MAXB) g_prog[threadIdx.x] = 0;
}

// ---- packed f32x2 helpers (sm_100+) ----
__device__ __forceinline__ ull pack2(float a, float b) {
    ull r; asm("mov.b64 %0,{%1,%2};" : "=l"(r) : "f"(a), "f"(b)); return r;
}
__device__ __forceinline__ void unpack2(ull v, float& a, float& b) {
    asm("mov.b64 {%0,%1},%2;" : "=f"(a), "=f"(b) : "l"(v));
}
__device__ __forceinline__ ull addx2(ull a, ull b) {
    ull r; asm("add.rn.f32x2 %0,%1,%2;" : "=l"(r) : "l"(a), "l"(b)); return r;
}
__device__ __forceinline__ ull mulx2(ull a, ull b) {
    ull r; asm("mul.rn.f32x2 %0,%1,%2;" : "=l"(r) : "l"(a), "l"(b)); return r;
}
__device__ __forceinline__ ull fma2_(ull a, ull b, ull c) {
    ull r; asm("fma.rn.f32x2 %0,%1,%2,%3;" : "=l"(r) : "l"(a), "l"(b), "l"(c)); return r;
}
__device__ __forceinline__ uint32_t redux_max_u32(uint32_t v) {
    uint32_t r; asm("redux.sync.max.u32 %0, %1, 0xffffffff;" : "=r"(r) : "r"(v)); return r;
}
__device__ __forceinline__ uint32_t redux_min_u32(uint32_t v) {
    uint32_t r; asm("redux.sync.min.u32 %0, %1, 0xffffffff;" : "=r"(r) : "r"(v)); return r;
}
__device__ __forceinline__ void st_release_gpu(int* p, int v) {
    asm volatile("st.release.gpu.global.s32 [%0], %1;" :: "l"(p), "r"(v) : "memory");
}
__device__ __forceinline__ int ld_acquire_gpu(const int* p) {
    int v; asm volatile("ld.acquire.gpu.global.s32 %0, [%1];" : "=r"(v) : "l"(p) : "memory");
    return v;
}
__device__ __forceinline__ uint32_t smem_u32(const void* p) {
    uint32_t a;
    asm("{ .reg .u64 t; cvta.to.shared.u64 t, %1; cvt.u32.u64 %0, t; }"
        : "=r"(a) : "l"(p));
    return a;
}
__device__ __forceinline__ void sts_release_cta(uint32_t addr, uint32_t v) {
    asm volatile("st.release.cta.shared.u32 [%0], %1;" :: "r"(addr), "r"(v) : "memory");
}
__device__ __forceinline__ uint32_t lds_acquire_cta(uint32_t addr) {
    uint32_t v;
    asm volatile("ld.acquire.cta.shared.u32 %0, [%1];" : "=r"(v) : "r"(addr) : "memory");
    return v;
}
__device__ __forceinline__ void sts_u32(uint32_t addr, uint32_t v) {
    asm volatile("st.shared.u32 [%0], %1;" :: "r"(addr), "r"(v) : "memory");
}

// ============================================================
// Fused kernel, TPB=512:
//   blocks [0, B)        : FPS, one per batch (exclusive SM)
//   blocks [B, B + 32*B) : kNN, 16 groups per block, batch-major order
// ============================================================
__global__ __launch_bounds__(TPB)
void fused_kernel(const float* __restrict__ xyz,
                  float* __restrict__ nb,
                  float* __restrict__ centers,
                  int N, int B) {
    extern __shared__ float s[];
    float* sx = s;
    float* sy = s + N;
    float* sz = s + 2 * N;

    const int tid  = threadIdx.x;
    const int lane = tid & 31;
    const int warp = tid >> 5;

    if (blockIdx.x < (unsigned)B) {
        // ==================== FPS: 16 points per thread ====================
        const int b = blockIdx.x;
        const float* X = xyz + (size_t)b * 3 * N;
        const float* Y = X + N;
        const float* Z = Y + N;

        __shared__ uint32_t vbuf[2][32];     // per-warp value table (lanes 16..31 stay 0)
        __shared__ uint32_t idslot[2];       // rare multi-warp-tie resolution
        __shared__ uint32_t pkt[2][4];       // [parity][cx, cy, cz, seq]
        if (tid < 64) vbuf[tid >> 5][tid & 31] = 0u;
        if (tid < 2)  { idslot[tid] = 0xFFFFFFFFu; pkt[tid][3] = 0u; }

        const uint32_t pkt_addr[2] = { smem_u32(&pkt[0][0]), smem_u32(&pkt[1][0]) };

        // 8 packed pairs per thread (N <= 8192)
        ull  pxp[8], pyp[8], pzp[8];
        float md[16];
        const int NP = (N + 2 * TPB - 1) / (2 * TPB);
        float2* sx2w = (float2*)sx;
        float2* sy2w = (float2*)sy;
        float2* sz2w = (float2*)sz;
        #pragma unroll
        for (int i = 0; i < 8; i++) {
            if (i < NP) {
                int p  = tid + i * TPB;
                int n0 = 2 * p;
                bool v = (n0 + 1 < N);
                float x0 = v ? X[n0] : 0.f, x1 = v ? X[n0 + 1] : 0.f;
                float y0 = v ? Y[n0] : 0.f, y1 = v ? Y[n0 + 1] : 0.f;
                float z0 = v ? Z[n0] : 0.f, z1 = v ? Z[n0 + 1] : 0.f;
                pxp[i] = pack2(x0, x1);
                pyp[i] = pack2(y0, y1);
                pzp[i] = pack2(z0, z1);
                md[2 * i]     = v ? 1e10f : -1.0f;
                md[2 * i + 1] = v ? 1e10f : -1.0f;
                if (v) {
                    sx2w[p] = make_float2(x0, x1);   // staged for winner coord fetch
                    sy2w[p] = make_float2(y0, y1);
                    sz2w[p] = make_float2(z0, z1);
                }
            }
        }

        float cx = X[0], cy = Y[0], cz = Z[0];
        float* cout = centers + (size_t)b * NUM_GROUP * 3;
        __syncthreads();

        for (int it = 0; it < NUM_GROUP; it++) {
            const int p = it & 1;
            if (tid == 0) {
                cout[it * 3 + 0] = cx;
                cout[it * 3 + 1] = cy;
                cout[it * 3 + 2] = cz;
                if ((it & 7) == 7) st_release_gpu(&g_prog[b], it - 7);   // lagged publish
            }
            if (it == NUM_GROUP - 1) break;    // last center stored; no selection needed

            const ull ncx = pack2(-cx, -cx), ncy = pack2(-cy, -cy), ncz = pack2(-cz, -cz);

            // lean hot loop: value-only tracking
            float bm0 = -2.0f, bm1 = -2.0f;
            #pragma unroll
            for (int i = 0; i < 8; i++) {
                if (i < NP) {
                    ull dx = addx2(pxp[i], ncx);
                    ull dy = addx2(pyp[i], ncy);
                    ull dz = addx2(pzp[i], ncz);
                    ull m  = mulx2(dx, dx);
                    m = fma2_(dy, dy, m);
                    m = fma2_(dz, dz, m);      // == fmaf(dz,dz,fmaf(dy,dy,dx*dx)) per lane
                    float d0, d1; unpack2(m, d0, d1);
                    float m0 = fminf(md[2 * i],     d0);
                    float m1 = fminf(md[2 * i + 1], d1);
                    md[2 * i]     = m0;
                    md[2 * i + 1] = m1;
                    bm0 = fmaxf(bm0, m0);
                    bm1 = fmaxf(bm1, m1);
                }
            }
            float bv = fmaxf(bm0, bm1);

            uint32_t fb   = (bv >= 0.0f) ? __float_as_uint(bv) : 0u;
            uint32_t wmax = redux_max_u32(fb);
            if (lane == 0) vbuf[p][warp] = wmax;
            __syncthreads();                            // bar A (the only barrier)

            if (tid == TPB - 1) idslot[p ^ 1] = 0xFFFFFFFFu;   // reset for it+1 slow path

            uint32_t v2 = vbuf[p][lane];
            uint32_t m2 = redux_max_u32(v2);            // block max (same in all warps)
            unsigned tiemask = __ballot_sync(FULL, v2 == m2) & 0xFFFFu;
            const uint32_t seq = (uint32_t)(it + 1);

            if (__popc(tiemask) == 1) {
                // fast path: unique winner warp resolves coords, others fall to spin
                if (warp == (__ffs(tiemask) - 1)) {
                    // parallel mask rescan: bit j set iff md[j]==bv (id monotone in j)
                    uint32_t msk = 0u;
                    #pragma unroll
                    for (int j = 0; j < 16; j++)
                        msk |= (md[j] == bv) ? (1u << j) : 0u;
                    uint32_t q = 0xFFFFFFFFu;
                    if (fb == m2 && msk) {
                        int j = __ffs(msk) - 1;
                        q = (uint32_t)(2 * (tid + (j >> 1) * TPB) + (j & 1));
                    }
                    uint32_t idmin = redux_min_u32(q);
                    if (q == idmin) {
                        float wx = sx[q], wy = sy[q], wz = sz[q];   // 3 parallel LDS
                        sts_u32(pkt_addr[p] + 0, __float_as_uint(wx));
                        sts_u32(pkt_addr[p] + 4, __float_as_uint(wy));
                        sts_u32(pkt_addr[p] + 8, __float_as_uint(wz));
                        sts_release_cta(pkt_addr[p] + 12, seq);     // coords before seq
                    }
                }
            } else {
                // rare exact-tie across warps (block-uniform branch)
                uint32_t q = 0xFFFFFFFFu;
                if (wmax == m2) {
                    uint32_t msk = 0u;
                    #pragma unroll
                    for (int j = 0; j < 16; j++)
                        msk |= (md[j] == bv) ? (1u << j) : 0u;
                    if (fb == m2 && msk) {
                        int j = __ffs(msk) - 1;
                        q = (uint32_t)(2 * (tid + (j >> 1) * TPB) + (j & 1));
                    }
                    uint32_t idw = redux_min_u32(q);
                    if (lane == 0) atomicMin(&idslot[p], idw);
                }
                __syncthreads();    // uniform: all warps took this branch
                if (q != 0xFFFFFFFFu && q == idslot[p]) {
                    float wx = sx[q], wy = sy[q], wz = sz[q];
                    sts_u32(pkt_addr[p] + 0, __float_as_uint(wx));
                    sts_u32(pkt_addr[p] + 4, __float_as_uint(wy));
                    sts_u32(pkt_addr[p] + 8, __float_as_uint(wz));
                    sts_release_cta(pkt_addr[p] + 12, seq);
                }
            }

            // all threads: spin until this iteration's packet is published
            while (lds_acquire_cta(pkt_addr[p] + 12) < seq) { }
            cx = __uint_as_float(pkt[p][0]);
            cy = __uint_as_float(pkt[p][1]);
            cz = __uint_as_float(pkt[p][2]);
        }
        if (tid == 0) st_release_gpu(&g_prog[b], NUM_GROUP);
    } else {
        // ==================== kNN top-32 (batch-major block order) ====================
        const int kb    = blockIdx.x - B;
        const int b     = kb % B;
        const int chunk = kb / B;
        const int g     = chunk * 16 + warp;

        const float* X = xyz + (size_t)b * 3 * N;
        const float4* X4 = (const float4*)X;
        float4* sx4 = (float4*)sx;
        float4* sy4 = (float4*)sy;
        float4* sz4 = (float4*)sz;
        const int N4 = N >> 2;
        for (int n = tid; n < N4; n += TPB) {
            sx4[n] = X4[n];
            sy4[n] = X4[N4 + n];
            sz4[n] = X4[2 * N4 + n];
        }
        __syncthreads();

        while (ld_acquire_gpu(&g_prog[b]) < g + 1) __nanosleep(128);

        const float* c = centers + ((size_t)b * NUM_GROUP + g) * 3;
        const float cx = __ldcg(&c[0]), cy = __ldcg(&c[1]), cz = __ldcg(&c[2]);

        // init with first 32 points, bitonic sort ascending u64 keys
        ull key;
        {
            float dx = sx[lane] - cx, dy = sy[lane] - cy, dz = sz[lane] - cz;
            float d2 = fmaf(dz, dz, fmaf(dy, dy, dx * dx));
            key = ((ull)__float_as_uint(d2) << 32) | (uint32_t)lane;
        }
        #pragma unroll
        for (int k2 = 2; k2 <= 32; k2 <<= 1) {
            #pragma unroll
            for (int j = k2 >> 1; j > 0; j >>= 1) {
                ull partner = __shfl_xor_sync(FULL, key, j);
                bool lower  = (lane & j) == 0;
                bool asc    = (lane & k2) == 0;
                ull mn = (key < partner) ? key : partner;
                ull mx = (key < partner) ? partner : key;
                key = (lower == asc) ? mn : mx;
            }
        }
        ull kmax = __shfl_sync(FULL, key, 31);

        // scalar step for points [32, 64)
        {
            int idx = 32 + lane;
            float dx = sx[idx] - cx, dy = sy[idx] - cy, dz = sz[idx] - cz;
            float d2 = fmaf(dz, dz, fmaf(dy, dy, dx * dx));
            ull nk = ((ull)__float_as_uint(d2) << 32) | (uint32_t)idx;
            unsigned mask = __ballot_sync(FULL, nk < kmax);
            while (mask) {
                int src = __ffs(mask) - 1;
                mask &= mask - 1;
                ull cand = __shfl_sync(FULL, nk, src);
                if (cand >= kmax) continue;
                int pos = __popc(__ballot_sync(FULL, key < cand));
                ull up  = __shfl_up_sync(FULL, key, 1);
                if (lane == pos)      key = cand;
                else if (lane > pos)  key = up;
                kmax = __shfl_sync(FULL, key, 31);
            }
        }

        // packed stream: 64 candidates per step
        const float2* sx2 = (const float2*)sx;
        const float2* sy2 = (const float2*)sy;
        const float2* sz2 = (const float2*)sz;
        const ull ncx = pack2(-cx, -cx), ncy = pack2(-cy, -cy), ncz = pack2(-cz, -cz);

        for (int base = 64; base < N; base += 64) {
            int h = (base >> 1) + lane;
            float2 xx = sx2[h], yy = sy2[h], zz = sz2[h];
            ull dx = addx2(pack2(xx.x, xx.y), ncx);
            ull dy = addx2(pack2(yy.x, yy.y), ncy);
            ull dz = addx2(pack2(zz.x, zz.y), ncz);
            ull m  = mulx2(dx, dx);
            m = fma2_(dy, dy, m);
            m = fma2_(dz, dz, m);
            float d0, d1; unpack2(m, d0, d1);
            int i0 = base + 2 * lane;
            ull k0 = ((ull)__float_as_uint(d0) << 32) | (uint32_t)i0;
            ull k1 = ((ull)__float_as_uint(d1) << 32) | (uint32_t)(i0 + 1);

            unsigned m0 = __ballot_sync(FULL, k0 < kmax);
            unsigned m1 = __ballot_sync(FULL, k1 < kmax);
            while (m0) {
                int src = __ffs(m0) - 1;
                m0 &= m0 - 1;
                ull cand = __shfl_sync(FULL, k0, src);
                if (cand >= kmax) continue;
                int pos = __popc(__ballot_sync(FULL, key < cand));
                ull up  = __shfl_up_sync(FULL, key, 1);
                if (lane == pos)      key = cand;
                else if (lane > pos)  key = up;
                kmax = __shfl_sync(FULL, key, 31);
            }
            while (m1) {
                int src = __ffs(m1) - 1;
                m1 &= m1 - 1;
                ull cand = __shfl_sync(FULL, k1, src);
                if (cand >= kmax) continue;
                int pos = __popc(__ballot_sync(FULL, key < cand));
                ull up  = __shfl_up_sync(FULL, key, 1);
                if (lane == pos)      key = cand;
                else if (lane > pos)  key = up;
                kmax = __shfl_sync(FULL, key, 31);
            }
        }

        // emit: neighborhood = point - center (lane-sorted ascending = top_k order)
        int idx = (int)(uint32_t)key;
        float ox = sx[idx] - cx, oy = sy[idx] - cy, oz = sz[idx] - cz;
        size_t o = (((size_t)b * NUM_GROUP + g) * GROUP_SIZE + lane) * 3;
        nb[o + 0] = ox;
        nb[o + 1] = oy;
        nb[o + 2] = oz;
    }
}

// ============================================================
extern "C" void kernel_launch(void* const* d_in, const int* in_sizes, int n_in,
                              void* d_out, int out_size) {
    const float* xyz = (const float*)d_in[0];
    float* out = (float*)d_out;

    const int B = out_size / (NUM_GROUP * (GROUP_SIZE + 1) * 3);
    const int N = in_sizes[0] / (3 * B);

    float* nb      = out;
    float* centers = out + (size_t)B * NUM_GROUP * GROUP_SIZE * 3;

    const int knnBlocks = B * (NUM_GROUP / 16);
    size_t smem = (size_t)3 * N * sizeof(float);
    if (smem < 120 * 1024) smem = 120 * 1024;   // force 1 block/SM

    init_prog<<<1, MAXB>>>();

    cudaFuncSetAttribute(fused_kernel, cudaFuncAttributeMaxDynamicSharedMemorySize, (int)smem);
    fused_kernel<<<B + knnBlocks, TPB, smem>>>(xyz, nb, centers, N, B);
}